// round 5
// baseline (speedup 1.0000x reference)
#include <cuda_runtime.h>
#include <cstdint>
#include <math.h>

#define HID 128
#define NEAR_T 0.01f
#define FAR_T 10.0f
#define MAX_IT 32
#define TILE_RAYS 128
#define NTHREADS 512
#define AST 136      // A row stride (words), conflict-free for frag loads
#define BST 136      // B row stride (words)

// ---- smem layout (float-word offsets) ----
#define OFF_BHI   0                      // 128*136 = 17408 : W2 hi, [k][n]
#define OFF_BLO   17408                  // 17408 : W2 lo
#define OFF_A     34816                  // 17408 : h1 fp32, [ray][k]
#define OFF_W1B   52224                  // 512 : (W1x,W1y,W1z,b1) per k
#define OFF_WC1B  52736                  // 512
#define OFF_WC2B  53248                  // 512
#define OFF_BW    53760                  // 256 : (b2[n], W3[n]) interleaved
#define OFF_BC2   54016                  // 4
#define OFF_PS    54020                  // 384 : ps[d*128 + ray]
#define OFF_PART  54404                  // 512 : part[ray*4 + ng]
#define OFF_INT   54916                  // sfrz[128], gfrz[4], stile
#define SMEM_WORDS 55056                 // 220224 bytes

__device__ int g_tile_ctr;
__global__ void reset_ctr_kernel() { g_tile_ctr = 0; }

__device__ __forceinline__ void mma_tf32(float* c, const uint32_t* a,
                                         uint32_t b0, uint32_t b1) {
    asm volatile(
        "mma.sync.aligned.m16n8k8.row.col.f32.tf32.tf32.f32 "
        "{%0,%1,%2,%3}, {%4,%5,%6,%7}, {%8,%9}, {%0,%1,%2,%3};"
        : "+f"(c[0]), "+f"(c[1]), "+f"(c[2]), "+f"(c[3])
        : "r"(a[0]), "r"(a[1]), "r"(a[2]), "r"(a[3]), "r"(b0), "r"(b1));
}

extern __shared__ float smem[];

__global__ void __launch_bounds__(NTHREADS, 1)
sphere_trace_kernel(const float* __restrict__ org,
                    const float* __restrict__ dir,
                    const float* __restrict__ W1, const float* __restrict__ b1,
                    const float* __restrict__ W2, const float* __restrict__ b2,
                    const float* __restrict__ W3, const float* __restrict__ b3,
                    const float* __restrict__ Wc1, const float* __restrict__ bc1,
                    const float* __restrict__ Wc2, const float* __restrict__ bc2,
                    float* __restrict__ out, int N, int ntiles)
{
    float* Bhi  = smem + OFF_BHI;
    float* Blo  = smem + OFF_BLO;
    float* Amat = smem + OFF_A;
    float* ps   = smem + OFF_PS;
    float* part = smem + OFF_PART;
    float* bw   = smem + OFF_BW;
    int*   sfrz = (int*)(smem + OFF_INT);
    int*   gfrz = sfrz + 128;
    int*   stile = gfrz + 4;

    const int t    = threadIdx.x;
    const int w    = t >> 5;
    const int lane = t & 31;
    const int gid  = lane >> 2;
    const int tig  = lane & 3;
    const int mg   = w >> 2;         // M group: rays [mg*32, mg*32+32)
    const int ng   = w & 3;          // N group: outs [ng*32, ng*32+32)

    // ---- one-time weight staging ----
    for (int idx = t; idx < 16384; idx += NTHREADS) {
        int k = idx >> 7, n = idx & 127;
        float v = W2[idx];                              // W2[k][n]
        uint32_t hu = __float_as_uint(v) & 0xFFFFE000u;
        Bhi[k * BST + n] = __uint_as_float(hu);
        Blo[k * BST + n] = v - __uint_as_float(hu);
    }
    if (t < 128) {
        float* w1b  = smem + OFF_W1B;
        float* wc1b = smem + OFF_WC1B;
        float* wc2b = smem + OFF_WC2B;
        w1b[t*4+0] = W1[t];         w1b[t*4+1] = W1[HID+t];
        w1b[t*4+2] = W1[2*HID+t];   w1b[t*4+3] = b1[t];
        wc1b[t*4+0] = Wc1[t];       wc1b[t*4+1] = Wc1[HID+t];
        wc1b[t*4+2] = Wc1[2*HID+t]; wc1b[t*4+3] = bc1[t];
        wc2b[t*4+0] = Wc2[3*t];     wc2b[t*4+1] = Wc2[3*t+1];
        wc2b[t*4+2] = Wc2[3*t+2];   wc2b[t*4+3] = 0.0f;
        bw[2*t]   = b2[t];
        bw[2*t+1] = W3[t];
    }
    if (t < 4) (smem + OFF_BC2)[t] = (t < 3) ? bc2[t] : 0.0f;
    const float bias3 = b3[0];

    // phase-A mapping: each thread -> 1 ray, 32 k
    const int aray = t >> 2;
    const int kseg = (t & 3) * 32;

    // GEMM pointers (fixed across tiles)
    const float* Abase = Amat + (mg * 32 + gid) * AST + tig;
    const float* pBh   = Bhi + tig * BST + ng * 32 + gid;
    const float* pBl   = Blo + tig * BST + ng * 32 + gid;

    __syncthreads();

    // ---- persistent tile loop ----
    for (;;) {
        if (t == 0) stile[0] = atomicAdd(&g_tile_ctr, 1);
        __syncthreads();
        const int tile = stile[0];
        if (tile >= ntiles) break;
        const int rbase = tile * TILE_RAYS;

        float dx = 0.f, dy = 0.f, dz = 0.f, dist = 0.f;
        bool hit = false, frozen = false;
        const int r = t & 127;
        if (t < 128) {
            int ray = rbase + r;
            if (ray >= N) ray = N - 1;
            ps[r]       = org[3*ray];
            ps[128 + r] = org[3*ray + 1];
            ps[256 + r] = org[3*ray + 2];
            dx = dir[3*ray]; dy = dir[3*ray + 1]; dz = dir[3*ray + 2];
            sfrz[r] = 0;
        }
        if (t < 4) gfrz[t] = 0;
        __syncthreads();

        for (int it = 0; it < MAX_IT; ++it) {
            // ===== phase A: layer 1 -> Amat[ray][k] (fp32) =====
            if (!sfrz[aray]) {
                const float px = ps[aray], py = ps[128 + aray], pz = ps[256 + aray];
                const float4* w1 = (const float4*)(smem + OFF_W1B);
                float* arow = Amat + aray * AST + kseg;
                #pragma unroll 4
                for (int kk = 0; kk < 32; kk += 4) {
                    float4 h4;
                    float4 q0 = w1[kseg + kk];
                    float4 q1 = w1[kseg + kk + 1];
                    float4 q2 = w1[kseg + kk + 2];
                    float4 q3 = w1[kseg + kk + 3];
                    h4.x = fmaxf(fmaf(px, q0.x, fmaf(py, q0.y, fmaf(pz, q0.z, q0.w))), 0.f);
                    h4.y = fmaxf(fmaf(px, q1.x, fmaf(py, q1.y, fmaf(pz, q1.z, q1.w))), 0.f);
                    h4.z = fmaxf(fmaf(px, q2.x, fmaf(py, q2.y, fmaf(pz, q2.z, q2.w))), 0.f);
                    h4.w = fmaxf(fmaf(px, q3.x, fmaf(py, q3.y, fmaf(pz, q3.z, q3.w))), 0.f);
                    *(float4*)(arow + kk) = h4;
                }
            }
            __syncthreads();

            // ===== phase B: layer 2 via mma.sync tf32 3-split + fused layer 3 =====
            if (!gfrz[mg]) {
                float c[2][4][4];
                #pragma unroll
                for (int mh = 0; mh < 2; ++mh)
                    #pragma unroll
                    for (int j = 0; j < 4; ++j)
                        #pragma unroll
                        for (int q = 0; q < 4; ++q) c[mh][j][q] = 0.0f;

                #pragma unroll 4
                for (int ks = 0; ks < 16; ++ks) {
                    uint32_t ahi[2][4], alo[2][4];
                    #pragma unroll
                    for (int mh = 0; mh < 2; ++mh) {
                        const float* ap = Abase + mh * (16 * AST) + ks * 8;
                        float a0 = ap[0], a1 = ap[8 * AST], a2 = ap[4], a3 = ap[8 * AST + 4];
                        uint32_t h0 = __float_as_uint(a0) & 0xFFFFE000u;
                        uint32_t h1_ = __float_as_uint(a1) & 0xFFFFE000u;
                        uint32_t h2 = __float_as_uint(a2) & 0xFFFFE000u;
                        uint32_t h3 = __float_as_uint(a3) & 0xFFFFE000u;
                        ahi[mh][0] = h0; ahi[mh][1] = h1_; ahi[mh][2] = h2; ahi[mh][3] = h3;
                        alo[mh][0] = __float_as_uint(a0 - __uint_as_float(h0));
                        alo[mh][1] = __float_as_uint(a1 - __uint_as_float(h1_));
                        alo[mh][2] = __float_as_uint(a2 - __uint_as_float(h2));
                        alo[mh][3] = __float_as_uint(a3 - __uint_as_float(h3));
                    }
                    #pragma unroll
                    for (int j = 0; j < 4; ++j) {
                        const float* bh = pBh + ks * (8 * BST) + j * 8;
                        const float* bl = pBl + ks * (8 * BST) + j * 8;
                        uint32_t b0h = __float_as_uint(bh[0]);
                        uint32_t b1h = __float_as_uint(bh[4 * BST]);
                        uint32_t b0l = __float_as_uint(bl[0]);
                        uint32_t b1l = __float_as_uint(bl[4 * BST]);
                        #pragma unroll
                        for (int mh = 0; mh < 2; ++mh) {
                            mma_tf32(c[mh][j], ahi[mh], b0h, b1h);
                            mma_tf32(c[mh][j], alo[mh], b0h, b1h);
                            mma_tf32(c[mh][j], ahi[mh], b0l, b1l);
                        }
                    }
                }

                // fused epilogue: relu(h2 + b2) . W3, reduce over n
                float rs[2][2] = {{0.f, 0.f}, {0.f, 0.f}};
                #pragma unroll
                for (int mh = 0; mh < 2; ++mh) {
                    #pragma unroll
                    for (int j = 0; j < 4; ++j) {
                        const int n0 = ng * 32 + j * 8 + tig * 2;
                        float4 bwv = *(const float4*)(bw + n0 * 2); // b2[n0],W3[n0],b2[n1],W3[n1]
                        rs[mh][0] = fmaf(fmaxf(c[mh][j][0] + bwv.x, 0.f), bwv.y, rs[mh][0]);
                        rs[mh][0] = fmaf(fmaxf(c[mh][j][1] + bwv.z, 0.f), bwv.w, rs[mh][0]);
                        rs[mh][1] = fmaf(fmaxf(c[mh][j][2] + bwv.x, 0.f), bwv.y, rs[mh][1]);
                        rs[mh][1] = fmaf(fmaxf(c[mh][j][3] + bwv.z, 0.f), bwv.w, rs[mh][1]);
                    }
                }
                // reduce across the 4 tig lanes (same rows)
                #pragma unroll
                for (int off = 1; off < 4; off <<= 1) {
                    rs[0][0] += __shfl_xor_sync(0xffffffffu, rs[0][0], off);
                    rs[0][1] += __shfl_xor_sync(0xffffffffu, rs[0][1], off);
                    rs[1][0] += __shfl_xor_sync(0xffffffffu, rs[1][0], off);
                    rs[1][1] += __shfl_xor_sync(0xffffffffu, rs[1][1], off);
                }
                if (tig == 0) {
                    const int row0 = mg * 32 + gid;
                    part[(row0)      * 4 + ng] = rs[0][0];
                    part[(row0 + 8)  * 4 + ng] = rs[0][1];
                    part[(row0 + 16) * 4 + ng] = rs[1][0];
                    part[(row0 + 24) * 4 + ng] = rs[1][1];
                }
            }
            __syncthreads();

            // ===== phase C: per-ray march update (owner threads t<128) =====
            int myfrozen = 1;
            if (t < 128) {
                myfrozen = frozen;
                if (!frozen) {
                    float4 pp = *(const float4*)(part + r * 4);
                    float sdf = bias3 + ((pp.x + pp.y) + (pp.z + pp.w));
                    const bool valid = (sdf <= NEAR_T) && (dist < FAR_T);
                    hit = hit || valid;
                    if (valid) {
                        frozen = true;
                        myfrozen = 1;
                        sfrz[r] = 1;
                    } else {
                        dist += sdf;
                        ps[r]       = fmaf(dx, sdf, ps[r]);
                        ps[128 + r] = fmaf(dy, sdf, ps[128 + r]);
                        ps[256 + r] = fmaf(dz, sdf, ps[256 + r]);
                    }
                }
                unsigned bal = __ballot_sync(0xffffffffu, myfrozen);
                if ((t & 31) == 0) gfrz[t >> 5] = (bal == 0xffffffffu) ? 1 : 0;
            }
            int alldone = __syncthreads_and(myfrozen);
            if (alldone) break;
        }

        // ===== color MLP (owner threads) =====
        if (t < 128 && (rbase + r) < N) {
            const float px = ps[r], py = ps[128 + r], pz = ps[256 + r];
            const bool mask = hit || (dist < FAR_T);
            const float* bc = smem + OFF_BC2;
            float c0 = bc[0], c1 = bc[1], c2 = bc[2];
            #pragma unroll 4
            for (int j = 0; j < HID; ++j) {
                float4 q  = *((const float4*)(smem + OFF_WC1B) + j);
                float4 wv = *((const float4*)(smem + OFF_WC2B) + j);
                float h = fmaf(px, q.x, fmaf(py, q.y, fmaf(pz, q.z, q.w)));
                h = fmaxf(h, 0.0f);
                c0 = fmaf(h, wv.x, c0);
                c1 = fmaf(h, wv.y, c1);
                c2 = fmaf(h, wv.z, c2);
            }
            const int oray = rbase + r;
            out[3*oray]     = mask ? (1.0f / (1.0f + expf(-c0))) : 0.0f;
            out[3*oray + 1] = mask ? (1.0f / (1.0f + expf(-c1))) : 0.0f;
            out[3*oray + 2] = mask ? (1.0f / (1.0f + expf(-c2))) : 0.0f;
        }
        __syncthreads();   // protect ps/part reuse across tiles
    }
}

extern "C" void kernel_launch(void* const* d_in, const int* in_sizes, int n_in,
                              void* d_out, int out_size)
{
    const float* org = (const float*)d_in[0];
    const float* dir = (const float*)d_in[1];
    const float* W1  = (const float*)d_in[2];
    const float* b1  = (const float*)d_in[3];
    const float* W2  = (const float*)d_in[4];
    const float* b2  = (const float*)d_in[5];
    const float* W3  = (const float*)d_in[6];
    const float* b3  = (const float*)d_in[7];
    const float* Wc1 = (const float*)d_in[8];
    const float* bc1 = (const float*)d_in[9];
    const float* Wc2 = (const float*)d_in[10];
    const float* bc2 = (const float*)d_in[11];
    float* out = (float*)d_out;

    const int N = in_sizes[0] / 3;
    const int ntiles = (N + TILE_RAYS - 1) / TILE_RAYS;
    const int smem_bytes = SMEM_WORDS * sizeof(float);

    cudaFuncSetAttribute(sphere_trace_kernel,
                         cudaFuncAttributeMaxDynamicSharedMemorySize, smem_bytes);

    reset_ctr_kernel<<<1, 1>>>();

    int nblocks = 152;
    if (nblocks > ntiles) nblocks = ntiles;
    sphere_trace_kernel<<<nblocks, NTHREADS, smem_bytes>>>(
        org, dir, W1, b1, W2, b2, W3, b3, Wc1, bc1, Wc2, bc2, out, N, ntiles);
}

// round 6
// speedup vs baseline: 2.3790x; 2.3790x over previous
#include <cuda_runtime.h>
#include <cuda_fp16.h>
#include <cstdint>
#include <math.h>

#define HID 128
#define NEAR_T 0.01f
#define FAR_T 10.0f
#define MAX_IT 32
#define TILE_RAYS 128
#define NTHREADS 512
#define ASTRIDE 68
#define INV2048 4.8828125e-4f

// ---- smem layout (float-word offsets) ----
#define OFF_BPK   0        // 16384 : B frags float4 (b0h,b1h,b0l,b1l) per (ks,jn,lane)
#define OFF_AH    16384    // 8704 : Ah[row][kpair] fp16x2, stride 68
#define OFF_AL    25088    // 8704 : Al (scaled 2048)
#define OFF_W1B   33792    // 512 : (W1x,W1y,W1z,b1) per k
#define OFF_WC1B  34304    // 512
#define OFF_WC2B  34816    // 512
#define OFF_BW    35328    // 256 : (b2[n], W3[n])
#define OFF_BC2   35584    // 4
#define OFF_PS    35588    // 384 : ps[d*128 + ray]
#define OFF_PART  35972    // 512 : part[ray*4 + ng]
#define OFF_INT   36484    // sfrz[128], gfrz[4], stile
#define SMEM_WORDS 36624   // 146496 bytes

__device__ int g_tile_ctr;
__global__ void reset_ctr_kernel() { g_tile_ctr = 0; }

__device__ __forceinline__ uint32_t h2u(__half2 h) {
    return *reinterpret_cast<uint32_t*>(&h);
}

__device__ __forceinline__ void mma16(float* c, const uint32_t* a,
                                      uint32_t b0, uint32_t b1) {
    asm volatile(
        "mma.sync.aligned.m16n8k16.row.col.f32.f16.f16.f32 "
        "{%0,%1,%2,%3}, {%4,%5,%6,%7}, {%8,%9}, {%0,%1,%2,%3};"
        : "+f"(c[0]), "+f"(c[1]), "+f"(c[2]), "+f"(c[3])
        : "r"(a[0]), "r"(a[1]), "r"(a[2]), "r"(a[3]), "r"(b0), "r"(b1));
}

extern __shared__ float smem[];

__global__ void __launch_bounds__(NTHREADS, 1)
sphere_trace_kernel(const float* __restrict__ org,
                    const float* __restrict__ dir,
                    const float* __restrict__ W1, const float* __restrict__ b1,
                    const float* __restrict__ W2, const float* __restrict__ b2,
                    const float* __restrict__ W3, const float* __restrict__ b3,
                    const float* __restrict__ Wc1, const float* __restrict__ bc1,
                    const float* __restrict__ Wc2, const float* __restrict__ bc2,
                    float* __restrict__ out, int N, int ntiles)
{
    float4*   Bpk = (float4*)(smem + OFF_BPK);
    uint32_t* Ah  = (uint32_t*)(smem + OFF_AH);
    uint32_t* Al  = (uint32_t*)(smem + OFF_AL);
    float* ps   = smem + OFF_PS;
    float* part = smem + OFF_PART;
    float* bw   = smem + OFF_BW;
    int*   sfrz = (int*)(smem + OFF_INT);
    int*   gfrz = sfrz + 128;
    int*   stile = gfrz + 4;

    const int t    = threadIdx.x;
    const int lane = t & 31;
    const int w    = t >> 5;
    const int gid  = lane >> 2;
    const int tig  = lane & 3;
    const int mg   = w >> 2;         // rays [mg*32, mg*32+32)
    const int ng   = w & 3;          // outs [ng*32, ng*32+32)

    // ---- B staging: W2[k][n] -> fp16 hi/lo frag-order float4s ----
    for (int idx = t; idx < 4096; idx += NTHREADS) {
        int ln = idx & 31, jn = (idx >> 5) & 15, ks = idx >> 9;
        int n  = jn * 8 + (ln >> 2);
        int k0 = ks * 16 + 2 * (ln & 3);
        float w00 = W2[k0*HID + n],     w01 = W2[(k0+1)*HID + n];
        float w10 = W2[(k0+8)*HID + n], w11 = W2[(k0+9)*HID + n];
        __half2 bh0 = __floats2half2_rn(w00, w01);
        __half2 bh1 = __floats2half2_rn(w10, w11);
        float2 r0 = __half22float2(bh0), r1 = __half22float2(bh1);
        __half2 bl0 = __floats2half2_rn((w00 - r0.x) * 2048.f, (w01 - r0.y) * 2048.f);
        __half2 bl1 = __floats2half2_rn((w10 - r1.x) * 2048.f, (w11 - r1.y) * 2048.f);
        Bpk[idx] = make_float4(__uint_as_float(h2u(bh0)), __uint_as_float(h2u(bh1)),
                               __uint_as_float(h2u(bl0)), __uint_as_float(h2u(bl1)));
    }
    if (t < 128) {
        float* w1b  = smem + OFF_W1B;
        float* wc1b = smem + OFF_WC1B;
        float* wc2b = smem + OFF_WC2B;
        w1b[t*4+0] = W1[t];         w1b[t*4+1] = W1[HID+t];
        w1b[t*4+2] = W1[2*HID+t];   w1b[t*4+3] = b1[t];
        wc1b[t*4+0] = Wc1[t];       wc1b[t*4+1] = Wc1[HID+t];
        wc1b[t*4+2] = Wc1[2*HID+t]; wc1b[t*4+3] = bc1[t];
        wc2b[t*4+0] = Wc2[3*t];     wc2b[t*4+1] = Wc2[3*t+1];
        wc2b[t*4+2] = Wc2[3*t+2];   wc2b[t*4+3] = 0.0f;
        bw[2*t]   = b2[t];
        bw[2*t+1] = W3[t];
    }
    if (t < 4) (smem + OFF_BC2)[t] = (t < 3) ? bc2[t] : 0.0f;
    const float bias3 = b3[0];

    // phase-A mapping: ray = w*8 + (t&7), kseg = (t>>3)&3 (bank-clean STS)
    const int aray  = w * 8 + (t & 7);
    const int akseg = (t >> 3) & 3;

    // GEMM A pointers (mh=0 row base)
    const uint32_t* pAh0 = Ah + (mg*32 + gid) * ASTRIDE + tig;
    const uint32_t* pAl0 = Al + (mg*32 + gid) * ASTRIDE + tig;

    __syncthreads();

    // ---- persistent tile loop ----
    for (;;) {
        if (t == 0) stile[0] = atomicAdd(&g_tile_ctr, 1);
        __syncthreads();
        const int tile = stile[0];
        if (tile >= ntiles) break;
        const int rbase = tile * TILE_RAYS;

        float dx = 0.f, dy = 0.f, dz = 0.f, dist = 0.f;
        bool hit = false, frozen = false;
        const int r = t & 127;
        if (t < 128) {
            int ray = rbase + r;
            if (ray >= N) ray = N - 1;
            ps[r]       = org[3*ray];
            ps[128 + r] = org[3*ray + 1];
            ps[256 + r] = org[3*ray + 2];
            dx = dir[3*ray]; dy = dir[3*ray + 1]; dz = dir[3*ray + 2];
            sfrz[r] = 0;
        }
        if (t < 4) gfrz[t] = 0;
        __syncthreads();

        for (int it = 0; it < MAX_IT; ++it) {
            // ===== phase A: layer 1 -> Ah/Al (fp16 hi + scaled lo, kpair packed) =====
            if (!sfrz[aray]) {
                const float px = ps[aray], py = ps[128 + aray], pz = ps[256 + aray];
                const float4* w1 = (const float4*)(smem + OFF_W1B);
                #pragma unroll
                for (int j = 0; j < 4; ++j) {
                    uint32_t hw[4], lw[4];
                    #pragma unroll
                    for (int q = 0; q < 4; ++q) {
                        int kp = akseg * 16 + j * 4 + q;
                        float4 q0 = w1[2*kp], q1 = w1[2*kp + 1];
                        float h0 = fmaxf(fmaf(px,q0.x,fmaf(py,q0.y,fmaf(pz,q0.z,q0.w))), 0.f);
                        float h1 = fmaxf(fmaf(px,q1.x,fmaf(py,q1.y,fmaf(pz,q1.z,q1.w))), 0.f);
                        __half2 hh = __floats2half2_rn(h0, h1);
                        float2 bk = __half22float2(hh);
                        __half2 ll = __floats2half2_rn((h0 - bk.x) * 2048.f,
                                                       (h1 - bk.y) * 2048.f);
                        hw[q] = h2u(hh);
                        lw[q] = h2u(ll);
                    }
                    int base = aray * ASTRIDE + akseg * 16 + j * 4;
                    *(uint4*)(Ah + base) = make_uint4(hw[0], hw[1], hw[2], hw[3]);
                    *(uint4*)(Al + base) = make_uint4(lw[0], lw[1], lw[2], lw[3]);
                }
            }
            __syncthreads();

            // ===== phase B: layer 2 via fp16 3-term mma + fused layer 3 =====
            if (!gfrz[mg]) {
                float ch[2][4][4], cl[2][4][4];
                #pragma unroll
                for (int mh = 0; mh < 2; ++mh)
                    #pragma unroll
                    for (int j = 0; j < 4; ++j)
                        #pragma unroll
                        for (int q = 0; q < 4; ++q) { ch[mh][j][q] = 0.f; cl[mh][j][q] = 0.f; }

                #pragma unroll
                for (int ks = 0; ks < 8; ++ks) {
                    uint32_t ah[2][4], al[2][4];
                    #pragma unroll
                    for (int mh = 0; mh < 2; ++mh) {
                        const uint32_t* ph = pAh0 + mh * (16*ASTRIDE) + ks * 8;
                        ah[mh][0] = ph[0];
                        ah[mh][1] = ph[8*ASTRIDE];
                        ah[mh][2] = ph[4];
                        ah[mh][3] = ph[8*ASTRIDE + 4];
                        const uint32_t* pl = pAl0 + mh * (16*ASTRIDE) + ks * 8;
                        al[mh][0] = pl[0];
                        al[mh][1] = pl[8*ASTRIDE];
                        al[mh][2] = pl[4];
                        al[mh][3] = pl[8*ASTRIDE + 4];
                    }
                    const float4* bp = Bpk + (ks * 16 + ng * 4) * 32 + lane;
                    #pragma unroll
                    for (int j = 0; j < 4; ++j) {
                        float4 bv = bp[j * 32];
                        uint32_t b0h = __float_as_uint(bv.x), b1h = __float_as_uint(bv.y);
                        uint32_t b0l = __float_as_uint(bv.z), b1l = __float_as_uint(bv.w);
                        #pragma unroll
                        for (int mh = 0; mh < 2; ++mh) {
                            mma16(ch[mh][j], ah[mh], b0h, b1h);   // Ah*Bh
                            mma16(cl[mh][j], al[mh], b0h, b1h);   // (2048*Al)*Bh
                            mma16(cl[mh][j], ah[mh], b0l, b1l);   // Ah*(2048*Bl)
                        }
                    }
                }

                // fused epilogue: h2 = ch + cl/2048 + b2; relu; dot W3; reduce over n
                float rs[2][2] = {{0.f, 0.f}, {0.f, 0.f}};
                #pragma unroll
                for (int mh = 0; mh < 2; ++mh) {
                    #pragma unroll
                    for (int j = 0; j < 4; ++j) {
                        const int n0 = ng * 32 + j * 8 + tig * 2;
                        float4 bwv = *(const float4*)(bw + n0 * 2);
                        float f0 = fmaf(cl[mh][j][0], INV2048, ch[mh][j][0]) + bwv.x;
                        float f1 = fmaf(cl[mh][j][1], INV2048, ch[mh][j][1]) + bwv.z;
                        float f2 = fmaf(cl[mh][j][2], INV2048, ch[mh][j][2]) + bwv.x;
                        float f3 = fmaf(cl[mh][j][3], INV2048, ch[mh][j][3]) + bwv.z;
                        rs[mh][0] = fmaf(fmaxf(f0, 0.f), bwv.y, rs[mh][0]);
                        rs[mh][0] = fmaf(fmaxf(f1, 0.f), bwv.w, rs[mh][0]);
                        rs[mh][1] = fmaf(fmaxf(f2, 0.f), bwv.y, rs[mh][1]);
                        rs[mh][1] = fmaf(fmaxf(f3, 0.f), bwv.w, rs[mh][1]);
                    }
                }
                #pragma unroll
                for (int off = 1; off < 4; off <<= 1) {
                    rs[0][0] += __shfl_xor_sync(0xffffffffu, rs[0][0], off);
                    rs[0][1] += __shfl_xor_sync(0xffffffffu, rs[0][1], off);
                    rs[1][0] += __shfl_xor_sync(0xffffffffu, rs[1][0], off);
                    rs[1][1] += __shfl_xor_sync(0xffffffffu, rs[1][1], off);
                }
                if (tig == 0) {
                    const int row0 = mg * 32 + gid;
                    part[(row0)      * 4 + ng] = rs[0][0];
                    part[(row0 + 8)  * 4 + ng] = rs[0][1];
                    part[(row0 + 16) * 4 + ng] = rs[1][0];
                    part[(row0 + 24) * 4 + ng] = rs[1][1];
                }
            }
            __syncthreads();

            // ===== phase C: per-ray march update (owner threads t<128) =====
            int myfrozen = 1;
            if (t < 128) {
                myfrozen = frozen;
                if (!frozen) {
                    float4 pp = *(const float4*)(part + r * 4);
                    float sdf = bias3 + ((pp.x + pp.y) + (pp.z + pp.w));
                    const bool valid = (sdf <= NEAR_T) && (dist < FAR_T);
                    hit = hit || valid;
                    if (valid) {
                        frozen = true;
                        myfrozen = 1;
                        sfrz[r] = 1;
                    } else {
                        dist += sdf;
                        ps[r]       = fmaf(dx, sdf, ps[r]);
                        ps[128 + r] = fmaf(dy, sdf, ps[128 + r]);
                        ps[256 + r] = fmaf(dz, sdf, ps[256 + r]);
                    }
                }
                unsigned bal = __ballot_sync(0xffffffffu, myfrozen);
                if ((t & 31) == 0) gfrz[t >> 5] = (bal == 0xffffffffu) ? 1 : 0;
            }
            int alldone = __syncthreads_and(myfrozen);
            if (alldone) break;
        }

        // ===== color MLP (owner threads) =====
        if (t < 128 && (rbase + r) < N) {
            const float px = ps[r], py = ps[128 + r], pz = ps[256 + r];
            const bool mask = hit || (dist < FAR_T);
            const float* bc = smem + OFF_BC2;
            float c0 = bc[0], c1 = bc[1], c2 = bc[2];
            #pragma unroll 4
            for (int j = 0; j < HID; ++j) {
                float4 q  = *((const float4*)(smem + OFF_WC1B) + j);
                float4 wv = *((const float4*)(smem + OFF_WC2B) + j);
                float h = fmaf(px, q.x, fmaf(py, q.y, fmaf(pz, q.z, q.w)));
                h = fmaxf(h, 0.0f);
                c0 = fmaf(h, wv.x, c0);
                c1 = fmaf(h, wv.y, c1);
                c2 = fmaf(h, wv.z, c2);
            }
            const int oray = rbase + r;
            out[3*oray]     = mask ? (1.0f / (1.0f + expf(-c0))) : 0.0f;
            out[3*oray + 1] = mask ? (1.0f / (1.0f + expf(-c1))) : 0.0f;
            out[3*oray + 2] = mask ? (1.0f / (1.0f + expf(-c2))) : 0.0f;
        }
        __syncthreads();   // protect ps/part/Ah reuse across tiles
    }
}

extern "C" void kernel_launch(void* const* d_in, const int* in_sizes, int n_in,
                              void* d_out, int out_size)
{
    const float* org = (const float*)d_in[0];
    const float* dir = (const float*)d_in[1];
    const float* W1  = (const float*)d_in[2];
    const float* b1  = (const float*)d_in[3];
    const float* W2  = (const float*)d_in[4];
    const float* b2  = (const float*)d_in[5];
    const float* W3  = (const float*)d_in[6];
    const float* b3  = (const float*)d_in[7];
    const float* Wc1 = (const float*)d_in[8];
    const float* bc1 = (const float*)d_in[9];
    const float* Wc2 = (const float*)d_in[10];
    const float* bc2 = (const float*)d_in[11];
    float* out = (float*)d_out;

    const int N = in_sizes[0] / 3;
    const int ntiles = (N + TILE_RAYS - 1) / TILE_RAYS;
    const int smem_bytes = SMEM_WORDS * sizeof(float);

    cudaFuncSetAttribute(sphere_trace_kernel,
                         cudaFuncAttributeMaxDynamicSharedMemorySize, smem_bytes);

    reset_ctr_kernel<<<1, 1>>>();

    int nblocks = 152;
    if (nblocks > ntiles) nblocks = ntiles;
    sphere_trace_kernel<<<nblocks, NTHREADS, smem_bytes>>>(
        org, dir, W1, b1, W2, b2, W3, b3, Wc1, bc1, Wc2, bc2, out, N, ntiles);
}

// round 7
// speedup vs baseline: 2.5179x; 1.0584x over previous
#include <cuda_runtime.h>
#include <cuda_fp16.h>
#include <cstdint>
#include <math.h>

#define HID 128
#define NEAR_T 0.01f
#define FAR_T 10.0f
#define MAX_IT 32
#define TILE_RAYS 64
#define NTHREADS 256
#define ASTRIDE 68
#define INV2048 4.8828125e-4f

// ---- smem layout (float-word offsets) ----
#define OFF_BPK   0        // 16384 : B frags float4 (b0h,b1h,b0l,b1l)
#define OFF_AH    16384    // 4352 : Ah[row][kpair] fp16x2, stride 68 (64 rows)
#define OFF_AL    20736    // 4352 : Al (scaled 2048)
#define OFF_W1B   25088    // 512 : (W1x,W1y,W1z,b1) per k
#define OFF_WC1B  25600    // 512
#define OFF_WC2B  26112    // 512
#define OFF_BW    26624    // 256 : (b2[n], W3[n])
#define OFF_BC2   26880    // 4
#define OFF_PS    26884    // 192 : ps[d*64 + ray]
#define OFF_PART  27076    // 256 : part[ray*4 + ng]
#define OFF_INT   27332    // sfrz[64], gfrz[2], stile
#define SMEM_WORDS 27408   // 109632 bytes -> 2 CTAs/SM

__device__ int g_tile_ctr;
__global__ void reset_ctr_kernel() { g_tile_ctr = 0; }

__device__ __forceinline__ uint32_t h2u(__half2 h) {
    return *reinterpret_cast<uint32_t*>(&h);
}

__device__ __forceinline__ void mma16(float* c, const uint32_t* a,
                                      uint32_t b0, uint32_t b1) {
    asm volatile(
        "mma.sync.aligned.m16n8k16.row.col.f32.f16.f16.f32 "
        "{%0,%1,%2,%3}, {%4,%5,%6,%7}, {%8,%9}, {%0,%1,%2,%3};"
        : "+f"(c[0]), "+f"(c[1]), "+f"(c[2]), "+f"(c[3])
        : "r"(a[0]), "r"(a[1]), "r"(a[2]), "r"(a[3]), "r"(b0), "r"(b1));
}

extern __shared__ float smem[];

__global__ void __launch_bounds__(NTHREADS, 2)
sphere_trace_kernel(const float* __restrict__ org,
                    const float* __restrict__ dir,
                    const float* __restrict__ W1, const float* __restrict__ b1,
                    const float* __restrict__ W2, const float* __restrict__ b2,
                    const float* __restrict__ W3, const float* __restrict__ b3,
                    const float* __restrict__ Wc1, const float* __restrict__ bc1,
                    const float* __restrict__ Wc2, const float* __restrict__ bc2,
                    float* __restrict__ out, int N, int ntiles)
{
    float4*   Bpk = (float4*)(smem + OFF_BPK);
    uint32_t* Ah  = (uint32_t*)(smem + OFF_AH);
    uint32_t* Al  = (uint32_t*)(smem + OFF_AL);
    float* ps   = smem + OFF_PS;
    float* part = smem + OFF_PART;
    float* bw   = smem + OFF_BW;
    int*   sfrz = (int*)(smem + OFF_INT);
    int*   gfrz = sfrz + 64;
    int*   stile = gfrz + 2;

    const int t    = threadIdx.x;
    const int lane = t & 31;
    const int w    = t >> 5;
    const int gid  = lane >> 2;
    const int tig  = lane & 3;
    const int mg   = w >> 2;         // 0..1 : rays [mg*32, mg*32+32)
    const int ng   = w & 3;          // 0..3 : outs [ng*32, ng*32+32)

    // ---- B staging: W2[k][n] -> fp16 hi/lo frag-order float4s ----
    for (int idx = t; idx < 4096; idx += NTHREADS) {
        int ln = idx & 31, jn = (idx >> 5) & 15, ks = idx >> 9;
        int n  = jn * 8 + (ln >> 2);
        int k0 = ks * 16 + 2 * (ln & 3);
        float w00 = W2[k0*HID + n],     w01 = W2[(k0+1)*HID + n];
        float w10 = W2[(k0+8)*HID + n], w11 = W2[(k0+9)*HID + n];
        __half2 bh0 = __floats2half2_rn(w00, w01);
        __half2 bh1 = __floats2half2_rn(w10, w11);
        float2 r0 = __half22float2(bh0), r1 = __half22float2(bh1);
        __half2 bl0 = __floats2half2_rn((w00 - r0.x) * 2048.f, (w01 - r0.y) * 2048.f);
        __half2 bl1 = __floats2half2_rn((w10 - r1.x) * 2048.f, (w11 - r1.y) * 2048.f);
        Bpk[idx] = make_float4(__uint_as_float(h2u(bh0)), __uint_as_float(h2u(bh1)),
                               __uint_as_float(h2u(bl0)), __uint_as_float(h2u(bl1)));
    }
    if (t < 128) {
        float* w1b  = smem + OFF_W1B;
        float* wc1b = smem + OFF_WC1B;
        float* wc2b = smem + OFF_WC2B;
        w1b[t*4+0] = W1[t];         w1b[t*4+1] = W1[HID+t];
        w1b[t*4+2] = W1[2*HID+t];   w1b[t*4+3] = b1[t];
        wc1b[t*4+0] = Wc1[t];       wc1b[t*4+1] = Wc1[HID+t];
        wc1b[t*4+2] = Wc1[2*HID+t]; wc1b[t*4+3] = bc1[t];
        wc2b[t*4+0] = Wc2[3*t];     wc2b[t*4+1] = Wc2[3*t+1];
        wc2b[t*4+2] = Wc2[3*t+2];   wc2b[t*4+3] = 0.0f;
        bw[2*t]   = b2[t];
        bw[2*t+1] = W3[t];
    }
    if (t < 4) (smem + OFF_BC2)[t] = (t < 3) ? bc2[t] : 0.0f;
    const float bias3 = b3[0];

    // phase-A mapping: each warp covers 8 rays x all k (4 ksegs per lane-octet)
    const int aray  = w * 8 + (t & 7);          // 0..63
    const int akseg = (t >> 3) & 3;

    // GEMM A pointers (mh=0 row base)
    const uint32_t* pAh0 = Ah + (mg*32 + gid) * ASTRIDE + tig;
    const uint32_t* pAl0 = Al + (mg*32 + gid) * ASTRIDE + tig;

    __syncthreads();

    // ---- persistent tile loop ----
    for (;;) {
        if (t == 0) stile[0] = atomicAdd(&g_tile_ctr, 1);
        __syncthreads();
        const int tile = stile[0];
        if (tile >= ntiles) break;
        const int rbase = tile * TILE_RAYS;

        float dx = 0.f, dy = 0.f, dz = 0.f, dist = 0.f;
        bool hit = false, frozen = false;
        const int r = t & 63;
        if (t < 64) {
            int ray = rbase + r;
            if (ray >= N) ray = N - 1;
            ps[r]       = org[3*ray];
            ps[64 + r]  = org[3*ray + 1];
            ps[128 + r] = org[3*ray + 2];
            dx = dir[3*ray]; dy = dir[3*ray + 1]; dz = dir[3*ray + 2];
            sfrz[r] = 0;
        }
        if (t < 2) gfrz[t] = 0;
        __syncthreads();

        for (int it = 0; it < MAX_IT; ++it) {
            // ===== phase A: layer 1 -> Ah/Al (fp16 hi + scaled lo) =====
            if (!sfrz[aray]) {
                const float px = ps[aray], py = ps[64 + aray], pz = ps[128 + aray];
                const float4* w1 = (const float4*)(smem + OFF_W1B);
                #pragma unroll
                for (int j = 0; j < 4; ++j) {
                    uint32_t hw[4], lw[4];
                    #pragma unroll
                    for (int q = 0; q < 4; ++q) {
                        int kp = akseg * 16 + j * 4 + q;
                        float4 q0 = w1[2*kp], q1 = w1[2*kp + 1];
                        float h0 = fmaxf(fmaf(px,q0.x,fmaf(py,q0.y,fmaf(pz,q0.z,q0.w))), 0.f);
                        float h1 = fmaxf(fmaf(px,q1.x,fmaf(py,q1.y,fmaf(pz,q1.z,q1.w))), 0.f);
                        __half2 hh = __floats2half2_rn(h0, h1);
                        float2 bk = __half22float2(hh);
                        __half2 ll = __floats2half2_rn((h0 - bk.x) * 2048.f,
                                                       (h1 - bk.y) * 2048.f);
                        hw[q] = h2u(hh);
                        lw[q] = h2u(ll);
                    }
                    int base = aray * ASTRIDE + akseg * 16 + j * 4;
                    *(uint4*)(Ah + base) = make_uint4(hw[0], hw[1], hw[2], hw[3]);
                    *(uint4*)(Al + base) = make_uint4(lw[0], lw[1], lw[2], lw[3]);
                }
            }
            __syncthreads();

            // ===== phase B: layer 2 via fp16 3-term mma + fused layer 3 =====
            if (!gfrz[mg]) {
                float ch[2][4][4], cl[2][4][4];
                #pragma unroll
                for (int mh = 0; mh < 2; ++mh)
                    #pragma unroll
                    for (int j = 0; j < 4; ++j)
                        #pragma unroll
                        for (int q = 0; q < 4; ++q) { ch[mh][j][q] = 0.f; cl[mh][j][q] = 0.f; }

                #pragma unroll
                for (int ks = 0; ks < 8; ++ks) {
                    uint32_t ah[2][4], al[2][4];
                    #pragma unroll
                    for (int mh = 0; mh < 2; ++mh) {
                        const uint32_t* ph = pAh0 + mh * (16*ASTRIDE) + ks * 8;
                        ah[mh][0] = ph[0];
                        ah[mh][1] = ph[8*ASTRIDE];
                        ah[mh][2] = ph[4];
                        ah[mh][3] = ph[8*ASTRIDE + 4];
                        const uint32_t* pl = pAl0 + mh * (16*ASTRIDE) + ks * 8;
                        al[mh][0] = pl[0];
                        al[mh][1] = pl[8*ASTRIDE];
                        al[mh][2] = pl[4];
                        al[mh][3] = pl[8*ASTRIDE + 4];
                    }
                    const float4* bp = Bpk + (ks * 16 + ng * 4) * 32 + lane;
                    #pragma unroll
                    for (int j = 0; j < 4; ++j) {
                        float4 bv = bp[j * 32];
                        uint32_t b0h = __float_as_uint(bv.x), b1h = __float_as_uint(bv.y);
                        uint32_t b0l = __float_as_uint(bv.z), b1l = __float_as_uint(bv.w);
                        #pragma unroll
                        for (int mh = 0; mh < 2; ++mh) {
                            mma16(ch[mh][j], ah[mh], b0h, b1h);   // Ah*Bh
                            mma16(cl[mh][j], al[mh], b0h, b1h);   // (2048*Al)*Bh
                            mma16(cl[mh][j], ah[mh], b0l, b1l);   // Ah*(2048*Bl)
                        }
                    }
                }

                // fused epilogue: h2 = ch + cl/2048 + b2; relu; dot W3; reduce over n
                float rs[2][2] = {{0.f, 0.f}, {0.f, 0.f}};
                #pragma unroll
                for (int mh = 0; mh < 2; ++mh) {
                    #pragma unroll
                    for (int j = 0; j < 4; ++j) {
                        const int n0 = ng * 32 + j * 8 + tig * 2;
                        float4 bwv = *(const float4*)(bw + n0 * 2);
                        float f0 = fmaf(cl[mh][j][0], INV2048, ch[mh][j][0]) + bwv.x;
                        float f1 = fmaf(cl[mh][j][1], INV2048, ch[mh][j][1]) + bwv.z;
                        float f2 = fmaf(cl[mh][j][2], INV2048, ch[mh][j][2]) + bwv.x;
                        float f3 = fmaf(cl[mh][j][3], INV2048, ch[mh][j][3]) + bwv.z;
                        rs[mh][0] = fmaf(fmaxf(f0, 0.f), bwv.y, rs[mh][0]);
                        rs[mh][0] = fmaf(fmaxf(f1, 0.f), bwv.w, rs[mh][0]);
                        rs[mh][1] = fmaf(fmaxf(f2, 0.f), bwv.y, rs[mh][1]);
                        rs[mh][1] = fmaf(fmaxf(f3, 0.f), bwv.w, rs[mh][1]);
                    }
                }
                #pragma unroll
                for (int off = 1; off < 4; off <<= 1) {
                    rs[0][0] += __shfl_xor_sync(0xffffffffu, rs[0][0], off);
                    rs[0][1] += __shfl_xor_sync(0xffffffffu, rs[0][1], off);
                    rs[1][0] += __shfl_xor_sync(0xffffffffu, rs[1][0], off);
                    rs[1][1] += __shfl_xor_sync(0xffffffffu, rs[1][1], off);
                }
                if (tig == 0) {
                    const int row0 = mg * 32 + gid;
                    part[(row0)      * 4 + ng] = rs[0][0];
                    part[(row0 + 8)  * 4 + ng] = rs[0][1];
                    part[(row0 + 16) * 4 + ng] = rs[1][0];
                    part[(row0 + 24) * 4 + ng] = rs[1][1];
                }
            }
            __syncthreads();

            // ===== phase C: per-ray march update (owner threads t<64) =====
            int myfrozen = 1;
            if (t < 64) {
                myfrozen = frozen;
                if (!frozen) {
                    float4 pp = *(const float4*)(part + r * 4);
                    float sdf = bias3 + ((pp.x + pp.y) + (pp.z + pp.w));
                    const bool valid = (sdf <= NEAR_T) && (dist < FAR_T);
                    hit = hit || valid;
                    if (valid) {
                        frozen = true;
                        myfrozen = 1;
                        sfrz[r] = 1;
                    } else {
                        dist += sdf;
                        ps[r]       = fmaf(dx, sdf, ps[r]);
                        ps[64 + r]  = fmaf(dy, sdf, ps[64 + r]);
                        ps[128 + r] = fmaf(dz, sdf, ps[128 + r]);
                    }
                }
                unsigned bal = __ballot_sync(0xffffffffu, myfrozen);
                if ((t & 31) == 0) gfrz[t >> 5] = (bal == 0xffffffffu) ? 1 : 0;
            }
            int alldone = __syncthreads_and(myfrozen);
            if (alldone) break;
        }

        // ===== color MLP (owner threads) =====
        if (t < 64 && (rbase + r) < N) {
            const float px = ps[r], py = ps[64 + r], pz = ps[128 + r];
            const bool mask = hit || (dist < FAR_T);
            const float* bc = smem + OFF_BC2;
            float c0 = bc[0], c1 = bc[1], c2 = bc[2];
            #pragma unroll 4
            for (int j = 0; j < HID; ++j) {
                float4 q  = *((const float4*)(smem + OFF_WC1B) + j);
                float4 wv = *((const float4*)(smem + OFF_WC2B) + j);
                float h = fmaf(px, q.x, fmaf(py, q.y, fmaf(pz, q.z, q.w)));
                h = fmaxf(h, 0.0f);
                c0 = fmaf(h, wv.x, c0);
                c1 = fmaf(h, wv.y, c1);
                c2 = fmaf(h, wv.z, c2);
            }
            const int oray = rbase + r;
            out[3*oray]     = mask ? (1.0f / (1.0f + expf(-c0))) : 0.0f;
            out[3*oray + 1] = mask ? (1.0f / (1.0f + expf(-c1))) : 0.0f;
            out[3*oray + 2] = mask ? (1.0f / (1.0f + expf(-c2))) : 0.0f;
        }
        __syncthreads();   // protect ps/part/Ah reuse across tiles
    }
}

extern "C" void kernel_launch(void* const* d_in, const int* in_sizes, int n_in,
                              void* d_out, int out_size)
{
    const float* org = (const float*)d_in[0];
    const float* dir = (const float*)d_in[1];
    const float* W1  = (const float*)d_in[2];
    const float* b1  = (const float*)d_in[3];
    const float* W2  = (const float*)d_in[4];
    const float* b2  = (const float*)d_in[5];
    const float* W3  = (const float*)d_in[6];
    const float* b3  = (const float*)d_in[7];
    const float* Wc1 = (const float*)d_in[8];
    const float* bc1 = (const float*)d_in[9];
    const float* Wc2 = (const float*)d_in[10];
    const float* bc2 = (const float*)d_in[11];
    float* out = (float*)d_out;

    const int N = in_sizes[0] / 3;
    const int ntiles = (N + TILE_RAYS - 1) / TILE_RAYS;
    const int smem_bytes = SMEM_WORDS * sizeof(float);

    cudaFuncSetAttribute(sphere_trace_kernel,
                         cudaFuncAttributeMaxDynamicSharedMemorySize, smem_bytes);

    reset_ctr_kernel<<<1, 1>>>();

    int nblocks = 304;                 // 2 persistent CTAs per SM
    if (nblocks > ntiles) nblocks = ntiles;
    sphere_trace_kernel<<<nblocks, NTHREADS, smem_bytes>>>(
        org, dir, W1, b1, W2, b2, W3, b3, Wc1, bc1, Wc2, bc2, out, N, ntiles);
}

// round 8
// speedup vs baseline: 3.1174x; 1.2381x over previous
#include <cuda_runtime.h>
#include <cuda_fp16.h>
#include <cstdint>
#include <math.h>

#define HID 128
#define NEAR_T 0.01f
#define FAR_T 10.0f
#define MAX_IT 32
#define TILE_RAYS 64
#define NTHREADS 256
#define ASTRIDE 68
#define INV2048 4.8828125e-4f

// ---- smem layout (float-word offsets) ----
#define OFF_BPK   0        // 16384 : B frags float4 (b0h,b1h,b0l,b1l)
#define OFF_AH    16384    // 4352 : Ah[row][kpair] fp16x2, stride 68 (64 rows)
#define OFF_AL    20736    // 4352 : Al (scaled 2048)
#define OFF_W1P   25088    // 544 : W1 interleaved, 4 kseg blocks of 136 words (bank-phased)
#define OFF_WC1B  25632    // 512
#define OFF_WC2B  26144    // 512
#define OFF_BW    26656    // 256 : (b2[n], W3[n])
#define OFF_BC2   26912    // 4
#define OFF_PART  26916    // 256 : part[ray*4 + ng]
#define OFF_WFRZ  27172    // 8 ints (16B aligned)
#define OFF_TILE  27180
#define SMEM_WORDS 27184   // 108736 bytes -> 2 CTAs/SM

__device__ int g_tile_ctr;
__global__ void reset_ctr_kernel() { g_tile_ctr = 0; }

__device__ __forceinline__ uint32_t h2u(__half2 h) {
    return *reinterpret_cast<uint32_t*>(&h);
}
__device__ __forceinline__ uint32_t smem_u32(const void* p) {
    uint32_t a;
    asm("{ .reg .u64 t; cvta.to.shared.u64 t, %1; cvt.u32.u64 %0, t; }" : "=r"(a) : "l"(p));
    return a;
}
__device__ __forceinline__ void mma16(float* c, const uint32_t* a,
                                      uint32_t b0, uint32_t b1) {
    asm volatile(
        "mma.sync.aligned.m16n8k16.row.col.f32.f16.f16.f32 "
        "{%0,%1,%2,%3}, {%4,%5,%6,%7}, {%8,%9}, {%0,%1,%2,%3};"
        : "+f"(c[0]), "+f"(c[1]), "+f"(c[2]), "+f"(c[3])
        : "r"(a[0]), "r"(a[1]), "r"(a[2]), "r"(a[3]), "r"(b0), "r"(b1));
}
__device__ __forceinline__ void ldsm4(uint32_t* r, uint32_t addr) {
    asm volatile("ldmatrix.sync.aligned.m8n8.x4.shared.b16 {%0,%1,%2,%3}, [%4];"
        : "=r"(r[0]), "=r"(r[1]), "=r"(r[2]), "=r"(r[3]) : "r"(addr));
}

// layer 1 for one ray, 32 k (kseg), write fp16 hi/lo to Ah/Al
__device__ __forceinline__ void compute_h1(const float4* w1blk, uint32_t* AhW, uint32_t* AlW,
                                           int aray, int akseg,
                                           float px, float py, float pz)
{
    #pragma unroll
    for (int j = 0; j < 4; ++j) {
        uint32_t hw[4], lw[4];
        #pragma unroll
        for (int q = 0; q < 4; ++q) {
            int kpl = j * 4 + q;
            float4 q0 = w1blk[kpl * 2], q1 = w1blk[kpl * 2 + 1];
            float h0 = fmaxf(fmaf(px, q0.x, fmaf(py, q0.y, fmaf(pz, q0.z, q0.w))), 0.f);
            float h1v = fmaxf(fmaf(px, q1.x, fmaf(py, q1.y, fmaf(pz, q1.z, q1.w))), 0.f);
            __half2 hh = __floats2half2_rn(h0, h1v);
            float2 bk = __half22float2(hh);
            __half2 ll = __floats2half2_rn((h0 - bk.x) * 2048.f, (h1v - bk.y) * 2048.f);
            hw[q] = h2u(hh);
            lw[q] = h2u(ll);
        }
        int base = aray * ASTRIDE + akseg * 16 + j * 4;
        *(uint4*)(AhW + base) = make_uint4(hw[0], hw[1], hw[2], hw[3]);
        *(uint4*)(AlW + base) = make_uint4(lw[0], lw[1], lw[2], lw[3]);
    }
}

extern __shared__ float smem[];

__global__ void __launch_bounds__(NTHREADS, 2)
sphere_trace_kernel(const float* __restrict__ org,
                    const float* __restrict__ dir,
                    const float* __restrict__ W1, const float* __restrict__ b1,
                    const float* __restrict__ W2, const float* __restrict__ b2,
                    const float* __restrict__ W3, const float* __restrict__ b3,
                    const float* __restrict__ Wc1, const float* __restrict__ bc1,
                    const float* __restrict__ Wc2, const float* __restrict__ bc2,
                    float* __restrict__ out, int N, int ntiles)
{
    float4*   Bpk = (float4*)(smem + OFF_BPK);
    uint32_t* AhW = (uint32_t*)(smem + OFF_AH);
    uint32_t* AlW = (uint32_t*)(smem + OFF_AL);
    float* part = smem + OFF_PART;
    float* bw   = smem + OFF_BW;
    int*   wfrz = (int*)(smem + OFF_WFRZ);
    int*   stile = (int*)(smem + OFF_TILE);

    const uint32_t sb = smem_u32(smem);
    const int t    = threadIdx.x;
    const int lane = t & 31;
    const int w    = t >> 5;
    const int gid  = lane >> 2;
    const int tig  = lane & 3;
    const int mg   = w >> 2;         // 0..1 : rays [mg*32, mg*32+32)
    const int ng   = w & 3;          // 0..3 : outs [ng*32, ng*32+32)
    const int aray  = w * 8 + (lane & 7);   // 0..63 (ray handled by this thread)
    const int akseg = lane >> 3;            // 0..3 (its 32-k segment)

    // ---- B staging: W2[k][n] -> fp16 hi/lo frag-order float4s ----
    for (int idx = t; idx < 4096; idx += NTHREADS) {
        int ln = idx & 31, jn = (idx >> 5) & 15, ks = idx >> 9;
        int n  = jn * 8 + (ln >> 2);
        int k0 = ks * 16 + 2 * (ln & 3);
        float w00 = W2[k0*HID + n],     w01 = W2[(k0+1)*HID + n];
        float w10 = W2[(k0+8)*HID + n], w11 = W2[(k0+9)*HID + n];
        __half2 bh0 = __floats2half2_rn(w00, w01);
        __half2 bh1 = __floats2half2_rn(w10, w11);
        float2 r0 = __half22float2(bh0), r1 = __half22float2(bh1);
        __half2 bl0 = __floats2half2_rn((w00 - r0.x) * 2048.f, (w01 - r0.y) * 2048.f);
        __half2 bl1 = __floats2half2_rn((w10 - r1.x) * 2048.f, (w11 - r1.y) * 2048.f);
        Bpk[idx] = make_float4(__uint_as_float(h2u(bh0)), __uint_as_float(h2u(bh1)),
                               __uint_as_float(h2u(bl0)), __uint_as_float(h2u(bl1)));
    }
    if (t < 128) {
        // W1P: per-kseg blocks of 34 float4 (136 words) => kseg phases 544B apart
        int kseg = t >> 5, klocal = t & 31, kpl = klocal >> 1, half = klocal & 1;
        ((float4*)(smem + OFF_W1P))[kseg * 34 + kpl * 2 + half] =
            make_float4(W1[t], W1[HID + t], W1[2*HID + t], b1[t]);
        float* wc1b = smem + OFF_WC1B;
        float* wc2b = smem + OFF_WC2B;
        wc1b[t*4+0] = Wc1[t];       wc1b[t*4+1] = Wc1[HID+t];
        wc1b[t*4+2] = Wc1[2*HID+t]; wc1b[t*4+3] = bc1[t];
        wc2b[t*4+0] = Wc2[3*t];     wc2b[t*4+1] = Wc2[3*t+1];
        wc2b[t*4+2] = Wc2[3*t+2];   wc2b[t*4+3] = 0.0f;
        bw[2*t]   = b2[t];
        bw[2*t+1] = W3[t];
    }
    if (t < 4) (smem + OFF_BC2)[t] = (t < 3) ? bc2[t] : 0.0f;
    const float bias3 = b3[0];

    const float4* w1blk = (const float4*)(smem + OFF_W1P) + akseg * 34;

    // ldmatrix lane base addresses (A fragments)
    const uint32_t ahAddr = sb + OFF_AH * 4
                          + (uint32_t)(mg * 32 + (lane & 15)) * 272
                          + (uint32_t)((lane >> 4) & 1) * 16;
    const uint32_t alAddr = ahAddr + (OFF_AL - OFF_AH) * 4;

    __syncthreads();

    // ---- persistent tile loop ----
    for (;;) {
        if (t == 0) stile[0] = atomicAdd(&g_tile_ctr, 1);
        __syncthreads();
        const int tile = stile[0];
        if (tile >= ntiles) break;
        const int rbase = tile * TILE_RAYS;

        int ray = rbase + aray;
        if (ray >= N) ray = N - 1;
        float px = org[3*ray], py = org[3*ray + 1], pz = org[3*ray + 2];
        const float dx = dir[3*ray], dy = dir[3*ray + 1], dz = dir[3*ray + 2];
        float dist = 0.f;
        bool hit = false, frozen = false;
        if (t < 8) wfrz[t] = 0;

        // A0: layer 1 at origins
        compute_h1(w1blk, AhW, AlW, aray, akseg, px, py, pz);
        __syncthreads();

        for (int it = 0; it < MAX_IT; ++it) {
            // ===== phase B: layer 2 fp16 3-term mma + fused layer 3 =====
            {
                int4 f4 = *((const int4*)wfrz + mg);
                if (!(f4.x & f4.y & f4.z & f4.w)) {
                    float ch[2][4][4], cl[2][4][4];
                    #pragma unroll
                    for (int mh = 0; mh < 2; ++mh)
                        #pragma unroll
                        for (int j = 0; j < 4; ++j)
                            #pragma unroll
                            for (int q = 0; q < 4; ++q) { ch[mh][j][q] = 0.f; cl[mh][j][q] = 0.f; }

                    #pragma unroll
                    for (int ks = 0; ks < 8; ++ks) {
                        uint32_t ah[2][4], al[2][4];
                        ldsm4(ah[0], ahAddr + ks * 32);
                        ldsm4(ah[1], ahAddr + 4352 + ks * 32);
                        ldsm4(al[0], alAddr + ks * 32);
                        ldsm4(al[1], alAddr + 4352 + ks * 32);
                        const float4* bp = Bpk + (ks * 16 + ng * 4) * 32 + lane;
                        #pragma unroll
                        for (int j = 0; j < 4; ++j) {
                            float4 bv = bp[j * 32];
                            uint32_t b0h = __float_as_uint(bv.x), b1h = __float_as_uint(bv.y);
                            uint32_t b0l = __float_as_uint(bv.z), b1l = __float_as_uint(bv.w);
                            #pragma unroll
                            for (int mh = 0; mh < 2; ++mh) {
                                mma16(ch[mh][j], ah[mh], b0h, b1h);   // Ah*Bh
                                mma16(cl[mh][j], al[mh], b0h, b1h);   // (2048*Al)*Bh
                                mma16(cl[mh][j], ah[mh], b0l, b1l);   // Ah*(2048*Bl)
                            }
                        }
                    }

                    // fused epilogue: h2 = ch + cl/2048 + b2; relu; dot W3; reduce over n
                    float rs[2][2] = {{0.f, 0.f}, {0.f, 0.f}};
                    #pragma unroll
                    for (int mh = 0; mh < 2; ++mh) {
                        #pragma unroll
                        for (int j = 0; j < 4; ++j) {
                            const int n0 = ng * 32 + j * 8 + tig * 2;
                            float4 bwv = *(const float4*)(bw + n0 * 2);
                            float f0 = fmaf(cl[mh][j][0], INV2048, ch[mh][j][0]) + bwv.x;
                            float f1 = fmaf(cl[mh][j][1], INV2048, ch[mh][j][1]) + bwv.z;
                            float f2 = fmaf(cl[mh][j][2], INV2048, ch[mh][j][2]) + bwv.x;
                            float f3 = fmaf(cl[mh][j][3], INV2048, ch[mh][j][3]) + bwv.z;
                            rs[mh][0] = fmaf(fmaxf(f0, 0.f), bwv.y, rs[mh][0]);
                            rs[mh][0] = fmaf(fmaxf(f1, 0.f), bwv.w, rs[mh][0]);
                            rs[mh][1] = fmaf(fmaxf(f2, 0.f), bwv.y, rs[mh][1]);
                            rs[mh][1] = fmaf(fmaxf(f3, 0.f), bwv.w, rs[mh][1]);
                        }
                    }
                    #pragma unroll
                    for (int off = 1; off < 4; off <<= 1) {
                        rs[0][0] += __shfl_xor_sync(0xffffffffu, rs[0][0], off);
                        rs[0][1] += __shfl_xor_sync(0xffffffffu, rs[0][1], off);
                        rs[1][0] += __shfl_xor_sync(0xffffffffu, rs[1][0], off);
                        rs[1][1] += __shfl_xor_sync(0xffffffffu, rs[1][1], off);
                    }
                    if (tig == 0) {
                        const int row0 = mg * 32 + gid;
                        part[(row0)      * 4 + ng] = rs[0][0];
                        part[(row0 + 8)  * 4 + ng] = rs[0][1];
                        part[(row0 + 16) * 4 + ng] = rs[1][0];
                        part[(row0 + 24) * 4 + ng] = rs[1][1];
                    }
                }
            }
            __syncthreads();

            // ===== fused phase C+A: march update in registers, then layer 1 =====
            {
                float s = part[w * 32 + (lane & 7) * 4 + akseg];
                s += __shfl_xor_sync(0xffffffffu, s, 8);
                s += __shfl_xor_sync(0xffffffffu, s, 16);
                float sdf = bias3 + s;
                if (!frozen) {
                    const bool valid = (sdf <= NEAR_T) && (dist < FAR_T);
                    hit = hit || valid;
                    if (valid) {
                        frozen = true;
                    } else {
                        dist += sdf;
                        px = fmaf(dx, sdf, px);
                        py = fmaf(dy, sdf, py);
                        pz = fmaf(dz, sdf, pz);
                        compute_h1(w1blk, AhW, AlW, aray, akseg, px, py, pz);
                    }
                }
                unsigned bal = __ballot_sync(0xffffffffu, frozen);
                if (lane == 0) wfrz[w] = (bal == 0xffffffffu) ? 1 : 0;
            }
            int alldone = __syncthreads_and(frozen);
            if (alldone) break;
        }

        // ===== color MLP (lanes 0-7 of each warp own rays w*8..w*8+7) =====
        if (lane < 8 && (rbase + aray) < N) {
            const bool mask = hit || (dist < FAR_T);
            const float* bc = smem + OFF_BC2;
            float c0 = bc[0], c1 = bc[1], c2 = bc[2];
            #pragma unroll 4
            for (int j = 0; j < HID; ++j) {
                float4 q  = *((const float4*)(smem + OFF_WC1B) + j);
                float4 wv = *((const float4*)(smem + OFF_WC2B) + j);
                float h = fmaf(px, q.x, fmaf(py, q.y, fmaf(pz, q.z, q.w)));
                h = fmaxf(h, 0.0f);
                c0 = fmaf(h, wv.x, c0);
                c1 = fmaf(h, wv.y, c1);
                c2 = fmaf(h, wv.z, c2);
            }
            const int oray = rbase + aray;
            out[3*oray]     = mask ? (1.0f / (1.0f + expf(-c0))) : 0.0f;
            out[3*oray + 1] = mask ? (1.0f / (1.0f + expf(-c1))) : 0.0f;
            out[3*oray + 2] = mask ? (1.0f / (1.0f + expf(-c2))) : 0.0f;
        }
        // tile-top barrier (after stile) orders Ah/part reuse across tiles
    }
}

extern "C" void kernel_launch(void* const* d_in, const int* in_sizes, int n_in,
                              void* d_out, int out_size)
{
    const float* org = (const float*)d_in[0];
    const float* dir = (const float*)d_in[1];
    const float* W1  = (const float*)d_in[2];
    const float* b1  = (const float*)d_in[3];
    const float* W2  = (const float*)d_in[4];
    const float* b2  = (const float*)d_in[5];
    const float* W3  = (const float*)d_in[6];
    const float* b3  = (const float*)d_in[7];
    const float* Wc1 = (const float*)d_in[8];
    const float* bc1 = (const float*)d_in[9];
    const float* Wc2 = (const float*)d_in[10];
    const float* bc2 = (const float*)d_in[11];
    float* out = (float*)d_out;

    const int N = in_sizes[0] / 3;
    const int ntiles = (N + TILE_RAYS - 1) / TILE_RAYS;
    const int smem_bytes = SMEM_WORDS * sizeof(float);

    cudaFuncSetAttribute(sphere_trace_kernel,
                         cudaFuncAttributeMaxDynamicSharedMemorySize, smem_bytes);

    reset_ctr_kernel<<<1, 1>>>();

    int nblocks = 304;                 // 2 persistent CTAs per SM
    if (nblocks > ntiles) nblocks = ntiles;
    sphere_trace_kernel<<<nblocks, NTHREADS, smem_bytes>>>(
        org, dir, W1, b1, W2, b2, W3, b3, Wc1, bc1, Wc2, bc2, out, N, ntiles);
}

// round 9
// speedup vs baseline: 3.2294x; 1.0359x over previous
#include <cuda_runtime.h>
#include <cuda_fp16.h>
#include <cstdint>
#include <math.h>

#define HID 128
#define NEAR_T 0.01f
#define FAR_T 10.0f
#define MAX_IT 32
#define TILE_RAYS 32        // per half-CTA worker
#define NTHREADS 256
#define ASTRIDE 68
#define AHALF 2176          // words per half A buffer (32*68)
#define INV2048 4.8828125e-4f

// ---- smem layout (float-word offsets) ----
#define OFF_BPK   0        // 16384 : B frags float4 (b0h,b1h,b0l,b1l)
#define OFF_AH    16384    // 4352 : Ah, 2 halves x 2176 words
#define OFF_AL    20736    // 4352 : Al (scaled 2048)
#define OFF_W1P   25088    // 544 : W1 interleaved, 4 kseg blocks (bank-phased)
#define OFF_WC1B  25632    // 512
#define OFF_WC2B  26144    // 512
#define OFF_BW    26656    // 256 : (b2[n], W3[n])
#define OFF_BC2   26912    // 4
#define OFF_PART  26916    // 256 : 2 halves x part[ray*4 + ng]
#define OFF_WFRZ  27172    // 8 ints : 2 halves x 4 warp flags
#define OFF_TILE  27180    // 2 ints
#define SMEM_WORDS 27184   // 108736 bytes -> 2 CTAs/SM

__device__ int g_tile_ctr;
__global__ void reset_ctr_kernel() { g_tile_ctr = 0; }

#define BAR_HALF(id) asm volatile("bar.sync %0, 128;" :: "r"(id) : "memory")

__device__ __forceinline__ uint32_t h2u(__half2 h) {
    return *reinterpret_cast<uint32_t*>(&h);
}
__device__ __forceinline__ uint32_t smem_u32(const void* p) {
    uint32_t a;
    asm("{ .reg .u64 t; cvta.to.shared.u64 t, %1; cvt.u32.u64 %0, t; }" : "=r"(a) : "l"(p));
    return a;
}
__device__ __forceinline__ void mma16(float* c, const uint32_t* a,
                                      uint32_t b0, uint32_t b1) {
    asm volatile(
        "mma.sync.aligned.m16n8k16.row.col.f32.f16.f16.f32 "
        "{%0,%1,%2,%3}, {%4,%5,%6,%7}, {%8,%9}, {%0,%1,%2,%3};"
        : "+f"(c[0]), "+f"(c[1]), "+f"(c[2]), "+f"(c[3])
        : "r"(a[0]), "r"(a[1]), "r"(a[2]), "r"(a[3]), "r"(b0), "r"(b1));
}
__device__ __forceinline__ void ldsm4(uint32_t* r, uint32_t addr) {
    asm volatile("ldmatrix.sync.aligned.m8n8.x4.shared.b16 {%0,%1,%2,%3}, [%4];"
        : "=r"(r[0]), "=r"(r[1]), "=r"(r[2]), "=r"(r[3]) : "r"(addr));
}

// layer 1 for one ray, 32 k (kseg), write fp16 hi/lo to Ah/Al (half-local)
__device__ __forceinline__ void compute_h1(const float4* w1blk, uint32_t* AhW, uint32_t* AlW,
                                           int aray, int akseg,
                                           float px, float py, float pz)
{
    #pragma unroll
    for (int j = 0; j < 4; ++j) {
        uint32_t hw[4], lw[4];
        #pragma unroll
        for (int q = 0; q < 4; ++q) {
            int kpl = j * 4 + q;
            float4 q0 = w1blk[kpl * 2], q1 = w1blk[kpl * 2 + 1];
            float h0 = fmaxf(fmaf(px, q0.x, fmaf(py, q0.y, fmaf(pz, q0.z, q0.w))), 0.f);
            float h1v = fmaxf(fmaf(px, q1.x, fmaf(py, q1.y, fmaf(pz, q1.z, q1.w))), 0.f);
            __half2 hh = __floats2half2_rn(h0, h1v);
            float2 bk = __half22float2(hh);
            __half2 ll = __floats2half2_rn((h0 - bk.x) * 2048.f, (h1v - bk.y) * 2048.f);
            hw[q] = h2u(hh);
            lw[q] = h2u(ll);
        }
        int base = aray * ASTRIDE + akseg * 16 + j * 4;
        *(uint4*)(AhW + base) = make_uint4(hw[0], hw[1], hw[2], hw[3]);
        *(uint4*)(AlW + base) = make_uint4(lw[0], lw[1], lw[2], lw[3]);
    }
}

extern __shared__ float smem[];

__global__ void __launch_bounds__(NTHREADS, 2)
sphere_trace_kernel(const float* __restrict__ org,
                    const float* __restrict__ dir,
                    const float* __restrict__ W1, const float* __restrict__ b1,
                    const float* __restrict__ W2, const float* __restrict__ b2,
                    const float* __restrict__ W3, const float* __restrict__ b3,
                    const float* __restrict__ Wc1, const float* __restrict__ bc1,
                    const float* __restrict__ Wc2, const float* __restrict__ bc2,
                    float* __restrict__ out, int N, int ntiles)
{
    float4* Bpk = (float4*)(smem + OFF_BPK);
    float*  bw  = smem + OFF_BW;
    int*    wfrz = (int*)(smem + OFF_WFRZ);
    int*    stile = (int*)(smem + OFF_TILE);

    const uint32_t sb = smem_u32(smem);
    const int t    = threadIdx.x;
    const int lane = t & 31;
    const int w    = t >> 5;
    const int half = t >> 7;            // 0 or 1 : independent worker
    const int wl   = w & 3;             // warp-in-half 0..3
    const int ng   = wl;                // N group : outs [ng*32, ng*32+32)
    const int gid  = lane >> 2;
    const int tig  = lane & 3;
    const int aray  = wl * 8 + (lane & 7);   // 0..31 half-local ray
    const int akseg = lane >> 3;             // 0..3
    const int barid = 1 + half;

    uint32_t* AhW = (uint32_t*)(smem + OFF_AH) + half * AHALF;
    uint32_t* AlW = (uint32_t*)(smem + OFF_AL) + half * AHALF;
    float*    part = smem + OFF_PART + half * 128;
    int*      wfrzH = wfrz + half * 4;

    // ---- one-time staging (whole CTA) ----
    for (int idx = t; idx < 4096; idx += NTHREADS) {
        int ln = idx & 31, jn = (idx >> 5) & 15, ks = idx >> 9;
        int n  = jn * 8 + (ln >> 2);
        int k0 = ks * 16 + 2 * (ln & 3);
        float w00 = W2[k0*HID + n],     w01 = W2[(k0+1)*HID + n];
        float w10 = W2[(k0+8)*HID + n], w11 = W2[(k0+9)*HID + n];
        __half2 bh0 = __floats2half2_rn(w00, w01);
        __half2 bh1 = __floats2half2_rn(w10, w11);
        float2 r0 = __half22float2(bh0), r1 = __half22float2(bh1);
        __half2 bl0 = __floats2half2_rn((w00 - r0.x) * 2048.f, (w01 - r0.y) * 2048.f);
        __half2 bl1 = __floats2half2_rn((w10 - r1.x) * 2048.f, (w11 - r1.y) * 2048.f);
        Bpk[idx] = make_float4(__uint_as_float(h2u(bh0)), __uint_as_float(h2u(bh1)),
                               __uint_as_float(h2u(bl0)), __uint_as_float(h2u(bl1)));
    }
    if (t < 128) {
        int kseg = t >> 5, klocal = t & 31, kpl = klocal >> 1, hh = klocal & 1;
        ((float4*)(smem + OFF_W1P))[kseg * 34 + kpl * 2 + hh] =
            make_float4(W1[t], W1[HID + t], W1[2*HID + t], b1[t]);
        float* wc1b = smem + OFF_WC1B;
        float* wc2b = smem + OFF_WC2B;
        wc1b[t*4+0] = Wc1[t];       wc1b[t*4+1] = Wc1[HID+t];
        wc1b[t*4+2] = Wc1[2*HID+t]; wc1b[t*4+3] = bc1[t];
        wc2b[t*4+0] = Wc2[3*t];     wc2b[t*4+1] = Wc2[3*t+1];
        wc2b[t*4+2] = Wc2[3*t+2];   wc2b[t*4+3] = 0.0f;
        bw[2*t]   = b2[t];
        bw[2*t+1] = W3[t];
    }
    if (t < 4) (smem + OFF_BC2)[t] = (t < 3) ? bc2[t] : 0.0f;
    const float bias3 = b3[0];
    __syncthreads();                  // last CTA-wide barrier

    const float4* w1blk = (const float4*)(smem + OFF_W1P) + akseg * 34;

    // ldmatrix lane base addresses (half-local A)
    const uint32_t ahAddr = sb + (OFF_AH + half * AHALF) * 4
                          + (uint32_t)(lane & 15) * 272
                          + (uint32_t)((lane >> 4) & 1) * 16;
    const uint32_t alAddr = ahAddr + (OFF_AL - OFF_AH) * 4;

    // ---- persistent per-half tile loop ----
    for (;;) {
        if ((t & 127) == 0) stile[half] = atomicAdd(&g_tile_ctr, 1);
        if (lane == 0) wfrzH[wl] = 0;
        BAR_HALF(barid);
        const int tile = stile[half];
        if (tile >= ntiles) break;
        const int rbase = tile * TILE_RAYS;

        int ray = rbase + aray;
        if (ray >= N) ray = N - 1;
        float px = org[3*ray], py = org[3*ray + 1], pz = org[3*ray + 2];
        const float dx = dir[3*ray], dy = dir[3*ray + 1], dz = dir[3*ray + 2];
        float dist = 0.f;
        bool hit = false, frozen = false;

        // A0: layer 1 at origins
        compute_h1(w1blk, AhW, AlW, aray, akseg, px, py, pz);

        for (int it = 0; it < MAX_IT; ++it) {
            BAR_HALF(barid);          // A writes + wfrz visible
            {
                int4 f4 = *(const int4*)wfrzH;
                if (f4.x & f4.y & f4.z & f4.w) break;   // all 32 rays frozen
            }

            // ===== phase B: layer 2 fp16 3-term mma + fused layer 3 =====
            {
                float ch[2][4][4], cl[2][4][4];
                #pragma unroll
                for (int mh = 0; mh < 2; ++mh)
                    #pragma unroll
                    for (int j = 0; j < 4; ++j)
                        #pragma unroll
                        for (int q = 0; q < 4; ++q) { ch[mh][j][q] = 0.f; cl[mh][j][q] = 0.f; }

                #pragma unroll
                for (int ks = 0; ks < 8; ++ks) {
                    uint32_t ah[2][4], al[2][4];
                    ldsm4(ah[0], ahAddr + ks * 32);
                    ldsm4(ah[1], ahAddr + 4352 + ks * 32);
                    ldsm4(al[0], alAddr + ks * 32);
                    ldsm4(al[1], alAddr + 4352 + ks * 32);
                    const float4* bp = Bpk + (ks * 16 + ng * 4) * 32 + lane;
                    #pragma unroll
                    for (int j = 0; j < 4; ++j) {
                        float4 bv = bp[j * 32];
                        uint32_t b0h = __float_as_uint(bv.x), b1h = __float_as_uint(bv.y);
                        uint32_t b0l = __float_as_uint(bv.z), b1l = __float_as_uint(bv.w);
                        #pragma unroll
                        for (int mh = 0; mh < 2; ++mh) {
                            mma16(ch[mh][j], ah[mh], b0h, b1h);   // Ah*Bh
                            mma16(cl[mh][j], al[mh], b0h, b1h);   // (2048*Al)*Bh
                            mma16(cl[mh][j], ah[mh], b0l, b1l);   // Ah*(2048*Bl)
                        }
                    }
                }

                float rs[2][2] = {{0.f, 0.f}, {0.f, 0.f}};
                #pragma unroll
                for (int mh = 0; mh < 2; ++mh) {
                    #pragma unroll
                    for (int j = 0; j < 4; ++j) {
                        const int n0 = ng * 32 + j * 8 + tig * 2;
                        float4 bwv = *(const float4*)(bw + n0 * 2);
                        float f0 = fmaf(cl[mh][j][0], INV2048, ch[mh][j][0]) + bwv.x;
                        float f1 = fmaf(cl[mh][j][1], INV2048, ch[mh][j][1]) + bwv.z;
                        float f2 = fmaf(cl[mh][j][2], INV2048, ch[mh][j][2]) + bwv.x;
                        float f3 = fmaf(cl[mh][j][3], INV2048, ch[mh][j][3]) + bwv.z;
                        rs[mh][0] = fmaf(fmaxf(f0, 0.f), bwv.y, rs[mh][0]);
                        rs[mh][0] = fmaf(fmaxf(f1, 0.f), bwv.w, rs[mh][0]);
                        rs[mh][1] = fmaf(fmaxf(f2, 0.f), bwv.y, rs[mh][1]);
                        rs[mh][1] = fmaf(fmaxf(f3, 0.f), bwv.w, rs[mh][1]);
                    }
                }
                #pragma unroll
                for (int off = 1; off < 4; off <<= 1) {
                    rs[0][0] += __shfl_xor_sync(0xffffffffu, rs[0][0], off);
                    rs[0][1] += __shfl_xor_sync(0xffffffffu, rs[0][1], off);
                    rs[1][0] += __shfl_xor_sync(0xffffffffu, rs[1][0], off);
                    rs[1][1] += __shfl_xor_sync(0xffffffffu, rs[1][1], off);
                }
                if (tig == 0) {
                    part[(gid)      * 4 + ng] = rs[0][0];
                    part[(gid + 8)  * 4 + ng] = rs[0][1];
                    part[(gid + 16) * 4 + ng] = rs[1][0];
                    part[(gid + 24) * 4 + ng] = rs[1][1];
                }
            }
            BAR_HALF(barid);          // part visible

            // ===== fused phase C+A: march update in regs, then layer 1 =====
            {
                float s = part[aray * 4 + akseg];
                s += __shfl_xor_sync(0xffffffffu, s, 8);
                s += __shfl_xor_sync(0xffffffffu, s, 16);
                float sdf = bias3 + s;
                if (!frozen) {
                    const bool valid = (sdf <= NEAR_T) && (dist < FAR_T);
                    hit = hit || valid;
                    if (valid) {
                        frozen = true;
                    } else {
                        dist += sdf;
                        px = fmaf(dx, sdf, px);
                        py = fmaf(dy, sdf, py);
                        pz = fmaf(dz, sdf, pz);
                        compute_h1(w1blk, AhW, AlW, aray, akseg, px, py, pz);
                    }
                }
                unsigned bal = __ballot_sync(0xffffffffu, frozen);
                if (lane == 0) wfrzH[wl] = (bal == 0xffffffffu) ? 1 : 0;
            }
        }

        // ===== color MLP: distributed over the 4 handler lanes per ray =====
        {
            const float* bc = smem + OFF_BC2;
            float c0 = 0.f, c1 = 0.f, c2 = 0.f;
            const float4* wc1b = (const float4*)(smem + OFF_WC1B) + akseg * 32;
            const float4* wc2b = (const float4*)(smem + OFF_WC2B) + akseg * 32;
            #pragma unroll 4
            for (int j = 0; j < 32; ++j) {
                float4 q  = wc1b[j];
                float4 wv = wc2b[j];
                float h = fmaf(px, q.x, fmaf(py, q.y, fmaf(pz, q.z, q.w)));
                h = fmaxf(h, 0.0f);
                c0 = fmaf(h, wv.x, c0);
                c1 = fmaf(h, wv.y, c1);
                c2 = fmaf(h, wv.z, c2);
            }
            c0 += __shfl_xor_sync(0xffffffffu, c0, 8);
            c1 += __shfl_xor_sync(0xffffffffu, c1, 8);
            c2 += __shfl_xor_sync(0xffffffffu, c2, 8);
            c0 += __shfl_xor_sync(0xffffffffu, c0, 16);
            c1 += __shfl_xor_sync(0xffffffffu, c1, 16);
            c2 += __shfl_xor_sync(0xffffffffu, c2, 16);
            if (lane < 8 && (rbase + aray) < N) {
                const bool mask = hit || (dist < FAR_T);
                c0 += bc[0]; c1 += bc[1]; c2 += bc[2];
                const int oray = rbase + aray;
                out[3*oray]     = mask ? (1.0f / (1.0f + expf(-c0))) : 0.0f;
                out[3*oray + 1] = mask ? (1.0f / (1.0f + expf(-c1))) : 0.0f;
                out[3*oray + 2] = mask ? (1.0f / (1.0f + expf(-c2))) : 0.0f;
            }
        }
        // loop-top barrier orders Ah/part reuse across tiles
    }
}

extern "C" void kernel_launch(void* const* d_in, const int* in_sizes, int n_in,
                              void* d_out, int out_size)
{
    const float* org = (const float*)d_in[0];
    const float* dir = (const float*)d_in[1];
    const float* W1  = (const float*)d_in[2];
    const float* b1  = (const float*)d_in[3];
    const float* W2  = (const float*)d_in[4];
    const float* b2  = (const float*)d_in[5];
    const float* W3  = (const float*)d_in[6];
    const float* b3  = (const float*)d_in[7];
    const float* Wc1 = (const float*)d_in[8];
    const float* bc1 = (const float*)d_in[9];
    const float* Wc2 = (const float*)d_in[10];
    const float* bc2 = (const float*)d_in[11];
    float* out = (float*)d_out;

    const int N = in_sizes[0] / 3;
    const int ntiles = (N + TILE_RAYS - 1) / TILE_RAYS;
    const int smem_bytes = SMEM_WORDS * sizeof(float);

    cudaFuncSetAttribute(sphere_trace_kernel,
                         cudaFuncAttributeMaxDynamicSharedMemorySize, smem_bytes);

    reset_ctr_kernel<<<1, 1>>>();

    int nblocks = 304;                 // 2 persistent CTAs per SM, 2 workers each
    sphere_trace_kernel<<<nblocks, NTHREADS, smem_bytes>>>(
        org, dir, W1, b1, W2, b2, W3, b3, Wc1, bc1, Wc2, bc2, out, N, ntiles);
}